// round 7
// baseline (speedup 1.0000x reference)
#include <cuda_runtime.h>
#include <cuda_fp16.h>

#define NN 100000
#define NE 3200000
#define BN_EPS 1e-5f
#define NSCAN 98   // ceil((NN+1)/1024)

// ---------------- scratch (static device buffers) ---------------------------
__device__ float4 g_h0[NN * 4];     // padded input features [N,16] (10 used)
__device__ float4 g_b0[NN * 4];     // combined layer-0 MLP input [N,16]
__device__ float4 g_a[NN * 16];     // MLP output pre-BN (post relu2) [N,64] fp32
__device__ float4 g_b[NN * 16];     // agg output: combined [N,64] fp32
__device__ __half g_ah[NN * 64];    // post-BN+ReLU activations, fp16
__device__ int   g_deg[NN];
__device__ int   g_rowstart[NN + 1];
__device__ int   g_cursor[NN];
__device__ int   g_src_sorted[NE];
__device__ int   g_blocksums[NSCAN];
__device__ int   g_blockoffs[NSCAN];
__device__ float g_stats[3 * 128];  // per layer: [0..63]=sum, [64..127]=sumsq

__device__ __forceinline__ float bnr(float v, float sc, float sh) {
    return fmaxf(fmaf(v, sc, sh), 0.0f);
}

// ---------------- packed f32x2 helpers (Blackwell FFMA2 path) ---------------
__device__ __forceinline__ unsigned long long packf2(float a, float b) {
    unsigned long long r;
    asm("mov.b64 %0, {%1, %2};" : "=l"(r) : "f"(a), "f"(b));
    return r;
}
__device__ __forceinline__ unsigned long long fma2(unsigned long long a,
                                                   unsigned long long b,
                                                   unsigned long long c) {
    unsigned long long d;
    asm("fma.rn.f32x2 %0, %1, %2, %3;" : "=l"(d) : "l"(a), "l"(b), "l"(c));
    return d;
}
__device__ __forceinline__ float2 unpackf2(unsigned long long v) {
    float2 r;
    asm("mov.b64 {%0, %1}, %2;" : "=f"(r.x), "=f"(r.y) : "l"(v));
    return r;
}

// ---------------- init + embed (fused) --------------------------------------
__global__ void k_init_embed(const float* __restrict__ x, const int* __restrict__ lab,
                             const float* __restrict__ emb) {
    int n = blockIdx.x * blockDim.x + threadIdx.x;
    if (n < 3 * 128) g_stats[n] = 0.0f;
    if (n >= NN) return;
    g_deg[n] = 0;
    const float* e = emb + lab[n] * 8;
    float x0 = x[2 * n], x1 = x[2 * n + 1];
    g_h0[n * 4 + 0] = make_float4(x0, x1, e[0], e[1]);
    g_h0[n * 4 + 1] = make_float4(e[2], e[3], e[4], e[5]);
    g_h0[n * 4 + 2] = make_float4(e[6], e[7], 0.0f, 0.0f);
    g_h0[n * 4 + 3] = make_float4(0.0f, 0.0f, 0.0f, 0.0f);
}

// ---------------- CSR build: histogram + scan + scatter ---------------------
__global__ void k_hist(const int4* __restrict__ dst4) {
    int e = blockIdx.x * blockDim.x + threadIdx.x;
    if (e >= NE / 4) return;
    int4 d = dst4[e];
    atomicAdd(&g_deg[d.x], 1);
    atomicAdd(&g_deg[d.y], 1);
    atomicAdd(&g_deg[d.z], 1);
    atomicAdd(&g_deg[d.w], 1);
}

__global__ void k_scanA() {
    __shared__ int sm[1024];
    int t = threadIdx.x;
    int i = blockIdx.x * 1024 + t;
    sm[t] = (i < NN) ? g_deg[i] : 0;
    __syncthreads();
    for (int off = 512; off > 0; off >>= 1) {
        if (t < off) sm[t] += sm[t + off];
        __syncthreads();
    }
    if (t == 0) g_blocksums[blockIdx.x] = sm[0];
}

__global__ void k_scanB() {
    __shared__ int s[NSCAN];
    int t = threadIdx.x;
    if (t < NSCAN) s[t] = g_blocksums[t];
    __syncthreads();
    if (t == 0) {
        int acc = 0;
        for (int b = 0; b < NSCAN; b++) { int v = s[b]; s[b] = acc; acc += v; }
    }
    __syncthreads();
    if (t < NSCAN) g_blockoffs[t] = s[t];
}

__global__ void k_scanC() {
    __shared__ int sm[1024];
    int t = threadIdx.x;
    int i = blockIdx.x * 1024 + t;
    int v = (i < NN) ? g_deg[i] : 0;
    sm[t] = v;
    __syncthreads();
    for (int off = 1; off < 1024; off <<= 1) {
        int add = (t >= off) ? sm[t - off] : 0;
        __syncthreads();
        sm[t] += add;
        __syncthreads();
    }
    int excl = g_blockoffs[blockIdx.x] + sm[t] - v;
    if (i <= NN) g_rowstart[i] = excl;
    if (i < NN)  g_cursor[i]   = excl;
}

__global__ void k_scatter(const int4* __restrict__ src4, const int4* __restrict__ dst4) {
    int e = blockIdx.x * blockDim.x + threadIdx.x;
    if (e >= NE / 4) return;
    int4 s = src4[e];
    int4 d = dst4[e];
    int p0 = atomicAdd(&g_cursor[d.x], 1); g_src_sorted[p0] = s.x;
    int p1 = atomicAdd(&g_cursor[d.y], 1); g_src_sorted[p1] = s.y;
    int p2 = atomicAdd(&g_cursor[d.z], 1); g_src_sorted[p2] = s.z;
    int p3 = atomicAdd(&g_cursor[d.w], 1); g_src_sorted[p3] = s.w;
}

// ---------------- layer-0 aggregation (16-wide rows, fp32) ------------------
// 4 threads/node, float4 lanes, 64 nodes/block
__global__ void k_agg0(const float* __restrict__ eps_ptr) {
    int t = threadIdx.x;
    int node = blockIdx.x * 64 + (t >> 2);
    if (node >= NN) return;
    int q = t & 3;
    int s = g_rowstart[node], e = g_rowstart[node + 1];
    float4 a0 = {0, 0, 0, 0}, a1 = {0, 0, 0, 0}, a2 = {0, 0, 0, 0}, a3 = {0, 0, 0, 0};
    int j = s;
    for (; j + 3 < e; j += 4) {
        int s0 = g_src_sorted[j], s1 = g_src_sorted[j + 1];
        int s2 = g_src_sorted[j + 2], s3 = g_src_sorted[j + 3];
        float4 v0 = g_h0[s0 * 4 + q], v1 = g_h0[s1 * 4 + q];
        float4 v2 = g_h0[s2 * 4 + q], v3 = g_h0[s3 * 4 + q];
        a0.x += v0.x; a0.y += v0.y; a0.z += v0.z; a0.w += v0.w;
        a1.x += v1.x; a1.y += v1.y; a1.z += v1.z; a1.w += v1.w;
        a2.x += v2.x; a2.y += v2.y; a2.z += v2.z; a2.w += v2.w;
        a3.x += v3.x; a3.y += v3.y; a3.z += v3.z; a3.w += v3.w;
    }
    for (; j < e; j++) {
        float4 v = g_h0[g_src_sorted[j] * 4 + q];
        a0.x += v.x; a0.y += v.y; a0.z += v.z; a0.w += v.w;
    }
    float c = 1.0f + *eps_ptr;
    float4 w = g_h0[node * 4 + q];
    float4 o;
    o.x = c * w.x + a0.x + a1.x + a2.x + a3.x;
    o.y = c * w.y + a0.y + a1.y + a2.y + a3.y;
    o.z = c * w.z + a0.z + a1.z + a2.z + a3.z;
    o.w = c * w.w + a0.w + a1.w + a2.w + a3.w;
    g_b0[node * 4 + q] = o;
}

// ---------------- BN apply + ReLU -> fp16: g_a (fp32) -> g_ah (half) --------
// one thread per feature pair; writes half2
__global__ void __launch_bounds__(256) k_bnapply(int lidx,
                                                 const float* __restrict__ gamma,
                                                 const float* __restrict__ beta) {
    __shared__ float ssc[64], ssh[64];
    int t = threadIdx.x;
    if (t < 64) {
        float mu = g_stats[lidx * 128 + t] * (1.0f / NN);
        float var = g_stats[lidx * 128 + 64 + t] * (1.0f / NN) - mu * mu;
        float r = rsqrtf(var + BN_EPS) * gamma[t];
        ssc[t] = r;
        ssh[t] = beta[t] - mu * r;
    }
    __syncthreads();
    int p = blockIdx.x * 256 + t;              // pair index, NN*32 total
    if (p >= NN * 32) return;
    int f2 = p & 31;                           // feature pair within row
    float2 v = ((const float2*)g_a)[p];
    float y0 = bnr(v.x, ssc[2 * f2], ssh[2 * f2]);
    float y1 = bnr(v.y, ssc[2 * f2 + 1], ssh[2 * f2 + 1]);
    ((__half2*)g_ah)[p] = __floats2half2_rn(y0, y1);
}

// ---------------- layers 1,2 aggregation: fp16 gather, fp32 accumulate ------
// WARP PER NODE: lane = (edge-group g 0..3) x (feature-quad q 0..7).
// Each group handles edges (j - s) % 4 == g; uniform trip count -> no
// intra-warp degree divergence. Cross-group reduce via shfl_xor(8,16).
__device__ __forceinline__ void accum8(float* a, uint4 v) {
    const __half2* h = (const __half2*)&v;
#pragma unroll
    for (int i = 0; i < 4; i++) {
        float2 f = __half22float2(h[i]);
        a[2 * i]     += f.x;
        a[2 * i + 1] += f.y;
    }
}

__global__ void __launch_bounds__(256) k_aggh(const float* __restrict__ eps_ptr) {
    int node = blockIdx.x * 8 + (threadIdx.x >> 5);   // 8 warps/block, 1 node/warp
    int lane = threadIdx.x & 31;
    int q = lane & 7;       // feature quad (8 halves)
    int g = lane >> 3;      // edge group 0..3
    const uint4* A = (const uint4*)g_ah;
    int s = g_rowstart[node], e = g_rowstart[node + 1];
    float a0[8] = {0, 0, 0, 0, 0, 0, 0, 0};
    float a1[8] = {0, 0, 0, 0, 0, 0, 0, 0};
    int j = s + g;
    for (; j + 4 < e; j += 8) {                       // 2 chains in flight
        int i0 = g_src_sorted[j];
        int i1 = g_src_sorted[j + 4];
        uint4 v0 = A[i0 * 8 + q];
        uint4 v1 = A[i1 * 8 + q];
        accum8(a0, v0);
        accum8(a1, v1);
    }
    if (j < e) accum8(a0, A[g_src_sorted[j] * 8 + q]);
#pragma unroll
    for (int i = 0; i < 8; i++) a0[i] += a1[i];
    // reduce across the 4 edge-groups (lanes differing in bits 3,4)
#pragma unroll
    for (int i = 0; i < 8; i++) {
        a0[i] += __shfl_xor_sync(0xffffffffu, a0[i], 8);
        a0[i] += __shfl_xor_sync(0xffffffffu, a0[i], 16);
    }
    if (g == 0) {
        float c = 1.0f + *eps_ptr;
        uint4 w = A[node * 8 + q];
        float self[8];
        const __half2* h = (const __half2*)&w;
#pragma unroll
        for (int i = 0; i < 4; i++) {
            float2 f = __half22float2(h[i]);
            self[2 * i] = f.x; self[2 * i + 1] = f.y;
        }
        float4 o0, o1;
        o0.x = fmaf(c, self[0], a0[0]);
        o0.y = fmaf(c, self[1], a0[1]);
        o0.z = fmaf(c, self[2], a0[2]);
        o0.w = fmaf(c, self[3], a0[3]);
        o1.x = fmaf(c, self[4], a0[4]);
        o1.y = fmaf(c, self[5], a0[5]);
        o1.z = fmaf(c, self[6], a0[6]);
        o1.w = fmaf(c, self[7], a0[7]);
        g_b[node * 16 + q * 2]     = o0;
        g_b[node * 16 + q * 2 + 1] = o1;
    }
}

// ---------------- fused 2-layer MLP + relu + BN partial stats ---------------
// block = 256 threads, 32 nodes. thread (f = t&63, g = t>>6) computes 8 nodes.
// Inner products use packed fma.rn.f32x2 (2 fp32 lanes/issue, exact IEEE fp32).
template <int DIN, int DINP>
__global__ void __launch_bounds__(256) k_mlp(const float* __restrict__ W1,
                                             const float* __restrict__ b1,
                                             const float* __restrict__ W2,
                                             const float* __restrict__ b2,
                                             int lidx) {
    __shared__ float sW1[DIN * 64];
    __shared__ float sW2[64 * 64];
    __shared__ float sA[DINP * 36];   // [k][node], stride 36 -> 16B-aligned rows
    __shared__ float sB[64 * 36];
    __shared__ float sred[256];
    __shared__ float qred[256];

    const float4* cbase = (DIN == 10) ? g_b0 : g_b;
    int t = threadIdx.x;
    int f = t & 63;
    int g = t >> 6;
    int node0 = blockIdx.x * 32;

    for (int i = t; i < DIN * 16; i += 256)
        ((float4*)sW1)[i] = ((const float4*)W1)[i];
    for (int i = t; i < 64 * 16; i += 256)
        ((float4*)sW2)[i] = ((const float4*)W2)[i];
    constexpr int Q = DINP / 4;               // float4s per node row
    for (int i = t; i < 32 * Q; i += 256) {
        int n = i / Q, kq = i % Q;
        float4 v = cbase[(node0 + n) * Q + kq];
        sA[(kq * 4 + 0) * 36 + n] = v.x;
        sA[(kq * 4 + 1) * 36 + n] = v.y;
        sA[(kq * 4 + 2) * 36 + n] = v.z;
        sA[(kq * 4 + 3) * 36 + n] = v.w;
    }
    __syncthreads();

    unsigned long long a01, a23, a45, a67;
    {
        float bb = b1[f];
        unsigned long long bp = packf2(bb, bb);
        a01 = bp; a23 = bp; a45 = bp; a67 = bp;
    }
#pragma unroll
    for (int k = 0; k < DIN; k++) {
        float w = sW1[k * 64 + f];
        unsigned long long ww = packf2(w, w);
        ulonglong2 p0 = *(const ulonglong2*)&sA[k * 36 + g * 8];
        ulonglong2 p1 = *(const ulonglong2*)&sA[k * 36 + g * 8 + 4];
        a01 = fma2(p0.x, ww, a01); a23 = fma2(p0.y, ww, a23);
        a45 = fma2(p1.x, ww, a45); a67 = fma2(p1.y, ww, a67);
    }
    {   // relu + write intermediate transposed: sB[f][n], two STS.128
        float2 v0 = unpackf2(a01), v1 = unpackf2(a23);
        float2 v2 = unpackf2(a45), v3 = unpackf2(a67);
        float4 y0 = make_float4(fmaxf(v0.x, 0.0f), fmaxf(v0.y, 0.0f),
                                fmaxf(v1.x, 0.0f), fmaxf(v1.y, 0.0f));
        float4 y1 = make_float4(fmaxf(v2.x, 0.0f), fmaxf(v2.y, 0.0f),
                                fmaxf(v3.x, 0.0f), fmaxf(v3.y, 0.0f));
        *(float4*)&sB[f * 36 + g * 8]     = y0;
        *(float4*)&sB[f * 36 + g * 8 + 4] = y1;
    }
    __syncthreads();

    {
        float bb = b2[f];
        unsigned long long bp = packf2(bb, bb);
        a01 = bp; a23 = bp; a45 = bp; a67 = bp;
    }
#pragma unroll
    for (int k = 0; k < 64; k++) {
        float w = sW2[k * 64 + f];
        unsigned long long ww = packf2(w, w);
        ulonglong2 p0 = *(const ulonglong2*)&sB[k * 36 + g * 8];
        ulonglong2 p1 = *(const ulonglong2*)&sB[k * 36 + g * 8 + 4];
        a01 = fma2(p0.x, ww, a01); a23 = fma2(p0.y, ww, a23);
        a45 = fma2(p1.x, ww, a45); a67 = fma2(p1.y, ww, a67);
    }

    float out8[8];
    {
        float2 v0 = unpackf2(a01), v1 = unpackf2(a23);
        float2 v2 = unpackf2(a45), v3 = unpackf2(a67);
        out8[0] = v0.x; out8[1] = v0.y; out8[2] = v1.x; out8[3] = v1.y;
        out8[4] = v2.x; out8[5] = v2.y; out8[6] = v3.x; out8[7] = v3.y;
    }

    float s = 0.0f, qq = 0.0f;
    float* ga = (float*)g_a;
#pragma unroll
    for (int i = 0; i < 8; i++) {
        float v = fmaxf(out8[i], 0.0f);
        ga[(node0 + g * 8 + i) * 64 + f] = v;
        s += v;
        qq += v * v;
    }
    sred[f * 4 + g] = s;
    qred[f * 4 + g] = qq;
    __syncthreads();
    if (t < 64) {
        float ss = sred[t * 4] + sred[t * 4 + 1] + sred[t * 4 + 2] + sred[t * 4 + 3];
        float q2 = qred[t * 4] + qred[t * 4 + 1] + qred[t * 4 + 2] + qred[t * 4 + 3];
        atomicAdd(&g_stats[lidx * 128 + t], ss);
        atomicAdd(&g_stats[lidx * 128 + 64 + t], q2);
    }
}

// ---------------- final: BN(layer2) + relu + linear head --------------------
__global__ void k_final(const float* __restrict__ gamma, const float* __restrict__ beta,
                        const float* __restrict__ Wf, const float* __restrict__ bf,
                        float* __restrict__ out) {
    int t = threadIdx.x;
    int lane = t & 31;
    int node = blockIdx.x * 8 + (t >> 5);
    const float* ga = (const float*)g_a;
    float total = 0.0f;
#pragma unroll
    for (int half = 0; half < 2; half++) {
        int f = lane + 32 * half;
        float mu = g_stats[2 * 128 + f] * (1.0f / NN);
        float var = g_stats[2 * 128 + 64 + f] * (1.0f / NN) - mu * mu;
        float v = (ga[node * 64 + f] - mu) * rsqrtf(var + BN_EPS) * gamma[f] + beta[f];
        total += fmaxf(v, 0.0f) * Wf[f];
    }
#pragma unroll
    for (int off = 16; off > 0; off >>= 1)
        total += __shfl_down_sync(0xffffffffu, total, off);
    if (lane == 0) out[node] = total + bf[0];
}

// ---------------- launch ----------------------------------------------------
extern "C" void kernel_launch(void* const* d_in, const int* in_sizes, int n_in,
                              void* d_out, int out_size) {
    const float* x       = (const float*)d_in[0];
    const int*   lab     = (const int*)d_in[1];
    const int*   ei      = (const int*)d_in[2];
    const float* emb     = (const float*)d_in[3];
    const float* W1_0    = (const float*)d_in[4];
    const float* b1_0    = (const float*)d_in[5];
    const float* W2_0    = (const float*)d_in[6];
    const float* b2_0    = (const float*)d_in[7];
    const float* eps_0   = (const float*)d_in[8];
    const float* gamma_0 = (const float*)d_in[9];
    const float* beta_0  = (const float*)d_in[10];
    const float* W1_s    = (const float*)d_in[11];
    const float* b1_s    = (const float*)d_in[12];
    const float* W2_s    = (const float*)d_in[13];
    const float* b2_s    = (const float*)d_in[14];
    const float* eps_s   = (const float*)d_in[15];
    const float* gamma_s = (const float*)d_in[16];
    const float* beta_s  = (const float*)d_in[17];
    const float* Wf      = (const float*)d_in[18];
    const float* bf      = (const float*)d_in[19];
    float* out = (float*)d_out;

    const int4* src4 = (const int4*)ei;
    const int4* dst4 = (const int4*)(ei + NE);

    k_init_embed<<<(NN + 255) / 256, 256>>>(x, lab, emb);

    // CSR build (counting sort by dst)
    k_hist<<<(NE / 4 + 255) / 256, 256>>>(dst4);
    k_scanA<<<NSCAN, 1024>>>();
    k_scanB<<<1, 128>>>();
    k_scanC<<<NSCAN, 1024>>>();
    k_scatter<<<(NE / 4 + 255) / 256, 256>>>(src4, dst4);

    // layer 0
    k_agg0<<<(NN + 63) / 64, 256>>>(eps_0);
    k_mlp<10, 16><<<NN / 32, 256>>>(W1_0, b1_0, W2_0, b2_0, 0);

    // layer 1: BN(l0) -> fp16, warp-per-node fp16 gather aggregation
    k_bnapply<<<(NN * 32 + 255) / 256, 256>>>(0, gamma_0, beta_0);
    k_aggh<<<NN / 8, 256>>>(eps_s + 0);
    k_mlp<64, 64><<<NN / 32, 256>>>(W1_s + 0 * 4096, b1_s + 0 * 64,
                                    W2_s + 0 * 4096, b2_s + 0 * 64, 1);

    // layer 2: BN(l1) -> fp16, warp-per-node fp16 gather aggregation
    k_bnapply<<<(NN * 32 + 255) / 256, 256>>>(1, gamma_s + 0 * 64, beta_s + 0 * 64);
    k_aggh<<<NN / 8, 256>>>(eps_s + 1);
    k_mlp<64, 64><<<NN / 32, 256>>>(W1_s + 1 * 4096, b1_s + 1 * 64,
                                    W2_s + 1 * 4096, b2_s + 1 * 64, 2);

    // final head (BN of layer 2 fused)
    k_final<<<NN / 8, 256>>>(gamma_s + 1 * 64, beta_s + 1 * 64, Wf, bf, out);
}

// round 8
// speedup vs baseline: 1.0678x; 1.0678x over previous
#include <cuda_runtime.h>
#include <cuda_fp16.h>

#define NN 100000
#define NE 3200000
#define BN_EPS 1e-5f
#define NSCAN 98   // ceil((NN+1)/1024)

// ---------------- scratch (static device buffers) ---------------------------
__device__ float4 g_h0[NN * 4];     // padded input features [N,16] (10 used)
__device__ float4 g_b0[NN * 4];     // combined layer-0 MLP input [N,16]
__device__ float4 g_a[NN * 16];     // MLP output pre-BN (post relu2) [N,64] fp32
__device__ float4 g_b[NN * 16];     // agg output: combined [N,64] fp32
__device__ __half g_ah[NN * 64];    // post-BN+ReLU activations, fp16
__device__ int   g_deg[NN];
__device__ int   g_rowstart[NN + 1];
__device__ int   g_cursor[NN];
__device__ int   g_src_sorted[NE];
__device__ int   g_blocksums[NSCAN];
__device__ float g_stats[3 * 128];  // per layer: [0..63]=sum, [64..127]=sumsq

__device__ __forceinline__ float bnr(float v, float sc, float sh) {
    return fmaxf(fmaf(v, sc, sh), 0.0f);
}

// ---------------- packed f32x2 helpers (Blackwell FFMA2 path) ---------------
__device__ __forceinline__ unsigned long long packf2(float a, float b) {
    unsigned long long r;
    asm("mov.b64 %0, {%1, %2};" : "=l"(r) : "f"(a), "f"(b));
    return r;
}
__device__ __forceinline__ unsigned long long fma2(unsigned long long a,
                                                   unsigned long long b,
                                                   unsigned long long c) {
    unsigned long long d;
    asm("fma.rn.f32x2 %0, %1, %2, %3;" : "=l"(d) : "l"(a), "l"(b), "l"(c));
    return d;
}
__device__ __forceinline__ float2 unpackf2(unsigned long long v) {
    float2 r;
    asm("mov.b64 {%0, %1}, %2;" : "=f"(r.x), "=f"(r.y) : "l"(v));
    return r;
}

// ---------------- init + embed (fused) --------------------------------------
__global__ void k_init_embed(const float* __restrict__ x, const int* __restrict__ lab,
                             const float* __restrict__ emb) {
    int n = blockIdx.x * blockDim.x + threadIdx.x;
    if (n < 3 * 128) g_stats[n] = 0.0f;
    if (n >= NN) return;
    g_deg[n] = 0;
    const float* e = emb + lab[n] * 8;
    float x0 = x[2 * n], x1 = x[2 * n + 1];
    g_h0[n * 4 + 0] = make_float4(x0, x1, e[0], e[1]);
    g_h0[n * 4 + 1] = make_float4(e[2], e[3], e[4], e[5]);
    g_h0[n * 4 + 2] = make_float4(e[6], e[7], 0.0f, 0.0f);
    g_h0[n * 4 + 3] = make_float4(0.0f, 0.0f, 0.0f, 0.0f);
}

// ---------------- CSR build: histogram + scan + scatter ---------------------
__global__ void k_hist(const int4* __restrict__ dst4) {
    int e = blockIdx.x * blockDim.x + threadIdx.x;
    if (e >= NE / 4) return;
    int4 d = dst4[e];
    atomicAdd(&g_deg[d.x], 1);
    atomicAdd(&g_deg[d.y], 1);
    atomicAdd(&g_deg[d.z], 1);
    atomicAdd(&g_deg[d.w], 1);
}

__global__ void k_scanA() {
    __shared__ int sm[1024];
    int t = threadIdx.x;
    int i = blockIdx.x * 1024 + t;
    sm[t] = (i < NN) ? g_deg[i] : 0;
    __syncthreads();
    for (int off = 512; off > 0; off >>= 1) {
        if (t < off) sm[t] += sm[t + off];
        __syncthreads();
    }
    if (t == 0) g_blocksums[blockIdx.x] = sm[0];
}

// scanC: per-block offset computed inline from g_blocksums (no scanB kernel)
__global__ void k_scanC() {
    __shared__ int sm[1024];
    __shared__ int boff;
    int t = threadIdx.x;
    if (t == 0) boff = 0;
    __syncthreads();
    if (t < (int)blockIdx.x) atomicAdd(&boff, g_blocksums[t]);  // t < 98 implied
    int i = blockIdx.x * 1024 + t;
    int v = (i < NN) ? g_deg[i] : 0;
    sm[t] = v;
    __syncthreads();
    for (int off = 1; off < 1024; off <<= 1) {
        int add = (t >= off) ? sm[t - off] : 0;
        __syncthreads();
        sm[t] += add;
        __syncthreads();
    }
    int excl = boff + sm[t] - v;
    if (i <= NN) g_rowstart[i] = excl;
    if (i < NN)  g_cursor[i]   = excl;
}

__global__ void k_scatter(const int* __restrict__ src, const int* __restrict__ dst) {
    int e = blockIdx.x * blockDim.x + threadIdx.x;
    if (e >= NE) return;
    int p = atomicAdd(&g_cursor[dst[e]], 1);
    g_src_sorted[p] = src[e];
}

// ---------------- layer-0 aggregation (16-wide rows, fp32) ------------------
// 4 threads/node, float4 lanes, 64 nodes/block
__global__ void k_agg0(const float* __restrict__ eps_ptr) {
    int t = threadIdx.x;
    int node = blockIdx.x * 64 + (t >> 2);
    if (node >= NN) return;
    int q = t & 3;
    int s = g_rowstart[node], e = g_rowstart[node + 1];
    float4 a0 = {0, 0, 0, 0}, a1 = {0, 0, 0, 0}, a2 = {0, 0, 0, 0}, a3 = {0, 0, 0, 0};
    int j = s;
    for (; j + 3 < e; j += 4) {
        int s0 = g_src_sorted[j], s1 = g_src_sorted[j + 1];
        int s2 = g_src_sorted[j + 2], s3 = g_src_sorted[j + 3];
        float4 v0 = g_h0[s0 * 4 + q], v1 = g_h0[s1 * 4 + q];
        float4 v2 = g_h0[s2 * 4 + q], v3 = g_h0[s3 * 4 + q];
        a0.x += v0.x; a0.y += v0.y; a0.z += v0.z; a0.w += v0.w;
        a1.x += v1.x; a1.y += v1.y; a1.z += v1.z; a1.w += v1.w;
        a2.x += v2.x; a2.y += v2.y; a2.z += v2.z; a2.w += v2.w;
        a3.x += v3.x; a3.y += v3.y; a3.z += v3.z; a3.w += v3.w;
    }
    for (; j < e; j++) {
        float4 v = g_h0[g_src_sorted[j] * 4 + q];
        a0.x += v.x; a0.y += v.y; a0.z += v.z; a0.w += v.w;
    }
    float c = 1.0f + *eps_ptr;
    float4 w = g_h0[node * 4 + q];
    float4 o;
    o.x = c * w.x + a0.x + a1.x + a2.x + a3.x;
    o.y = c * w.y + a0.y + a1.y + a2.y + a3.y;
    o.z = c * w.z + a0.z + a1.z + a2.z + a3.z;
    o.w = c * w.w + a0.w + a1.w + a2.w + a3.w;
    g_b0[node * 4 + q] = o;
}

// ---------------- BN apply + ReLU -> fp16: g_a (fp32) -> g_ah (half) --------
__global__ void __launch_bounds__(256) k_bnapply(int lidx,
                                                 const float* __restrict__ gamma,
                                                 const float* __restrict__ beta) {
    __shared__ float ssc[64], ssh[64];
    int t = threadIdx.x;
    if (t < 64) {
        float mu = g_stats[lidx * 128 + t] * (1.0f / NN);
        float var = g_stats[lidx * 128 + 64 + t] * (1.0f / NN) - mu * mu;
        float r = rsqrtf(var + BN_EPS) * gamma[t];
        ssc[t] = r;
        ssh[t] = beta[t] - mu * r;
    }
    __syncthreads();
    int p = blockIdx.x * 256 + t;              // pair index, NN*32 total
    if (p >= NN * 32) return;
    int f2 = p & 31;                           // feature pair within row
    float2 v = ((const float2*)g_a)[p];
    float y0 = bnr(v.x, ssc[2 * f2], ssh[2 * f2]);
    float y1 = bnr(v.y, ssc[2 * f2 + 1], ssh[2 * f2 + 1]);
    ((__half2*)g_ah)[p] = __floats2half2_rn(y0, y1);
}

// ---------------- layers 1,2 aggregation: fp16 gather, fp32 accumulate ------
// 8 threads/node, LDG.128 = 8 halves each, 32 nodes/block. reads g_ah -> g_b.
// (R5 form: best measured. 4 edges/iter in flight per thread.)
__device__ __forceinline__ void accum8(float* a, uint4 v) {
    const __half2* h = (const __half2*)&v;
#pragma unroll
    for (int i = 0; i < 4; i++) {
        float2 f = __half22float2(h[i]);
        a[2 * i]     += f.x;
        a[2 * i + 1] += f.y;
    }
}

__global__ void __launch_bounds__(256) k_aggh(const float* __restrict__ eps_ptr) {
    int t = threadIdx.x;
    int node = blockIdx.x * 32 + (t >> 3);
    int q = t & 7;
    const uint4* A = (const uint4*)g_ah;       // [N*8] uint4 rows of 8 halves
    int s = g_rowstart[node], e = g_rowstart[node + 1];
    float a0[8] = {0, 0, 0, 0, 0, 0, 0, 0};
    float a1[8] = {0, 0, 0, 0, 0, 0, 0, 0};
    int j = s;
    for (; j + 3 < e; j += 4) {
        int s0 = g_src_sorted[j],     s1 = g_src_sorted[j + 1];
        int s2 = g_src_sorted[j + 2], s3 = g_src_sorted[j + 3];
        uint4 v0 = A[s0 * 8 + q], v1 = A[s1 * 8 + q];
        uint4 v2 = A[s2 * 8 + q], v3 = A[s3 * 8 + q];
        accum8(a0, v0); accum8(a1, v1); accum8(a0, v2); accum8(a1, v3);
    }
    for (; j < e; j++) accum8(a0, A[g_src_sorted[j] * 8 + q]);

    float c = 1.0f + *eps_ptr;
    uint4 w = A[node * 8 + q];
    float self[8];
    {
        const __half2* h = (const __half2*)&w;
#pragma unroll
        for (int i = 0; i < 4; i++) {
            float2 f = __half22float2(h[i]);
            self[2 * i] = f.x; self[2 * i + 1] = f.y;
        }
    }
    float4 o0, o1;
    o0.x = fmaf(c, self[0], a0[0] + a1[0]);
    o0.y = fmaf(c, self[1], a0[1] + a1[1]);
    o0.z = fmaf(c, self[2], a0[2] + a1[2]);
    o0.w = fmaf(c, self[3], a0[3] + a1[3]);
    o1.x = fmaf(c, self[4], a0[4] + a1[4]);
    o1.y = fmaf(c, self[5], a0[5] + a1[5]);
    o1.z = fmaf(c, self[6], a0[6] + a1[6]);
    o1.w = fmaf(c, self[7], a0[7] + a1[7]);
    g_b[node * 16 + q * 2]     = o0;
    g_b[node * 16 + q * 2 + 1] = o1;
}

// ---------------- fused 2-layer MLP + relu + BN partial stats ---------------
// block = 256 threads, 32 nodes. thread (f = t&63, g = t>>6) computes 8 nodes.
// Inner products use packed fma.rn.f32x2 (2 fp32 lanes/issue, exact IEEE fp32).
template <int DIN, int DINP>
__global__ void __launch_bounds__(256) k_mlp(const float* __restrict__ W1,
                                             const float* __restrict__ b1,
                                             const float* __restrict__ W2,
                                             const float* __restrict__ b2,
                                             int lidx) {
    __shared__ float sW1[DIN * 64];
    __shared__ float sW2[64 * 64];
    __shared__ float sA[DINP * 36];   // [k][node], stride 36 -> 16B-aligned rows
    __shared__ float sB[64 * 36];
    __shared__ float sred[256];
    __shared__ float qred[256];

    const float4* cbase = (DIN == 10) ? g_b0 : g_b;
    int t = threadIdx.x;
    int f = t & 63;
    int g = t >> 6;
    int node0 = blockIdx.x * 32;

    for (int i = t; i < DIN * 16; i += 256)
        ((float4*)sW1)[i] = ((const float4*)W1)[i];
    for (int i = t; i < 64 * 16; i += 256)
        ((float4*)sW2)[i] = ((const float4*)W2)[i];
    constexpr int Q = DINP / 4;               // float4s per node row
    for (int i = t; i < 32 * Q; i += 256) {
        int n = i / Q, kq = i % Q;
        float4 v = cbase[(node0 + n) * Q + kq];
        sA[(kq * 4 + 0) * 36 + n] = v.x;
        sA[(kq * 4 + 1) * 36 + n] = v.y;
        sA[(kq * 4 + 2) * 36 + n] = v.z;
        sA[(kq * 4 + 3) * 36 + n] = v.w;
    }
    __syncthreads();

    unsigned long long a01, a23, a45, a67;
    {
        float bb = b1[f];
        unsigned long long bp = packf2(bb, bb);
        a01 = bp; a23 = bp; a45 = bp; a67 = bp;
    }
#pragma unroll
    for (int k = 0; k < DIN; k++) {
        float w = sW1[k * 64 + f];
        unsigned long long ww = packf2(w, w);
        ulonglong2 p0 = *(const ulonglong2*)&sA[k * 36 + g * 8];
        ulonglong2 p1 = *(const ulonglong2*)&sA[k * 36 + g * 8 + 4];
        a01 = fma2(p0.x, ww, a01); a23 = fma2(p0.y, ww, a23);
        a45 = fma2(p1.x, ww, a45); a67 = fma2(p1.y, ww, a67);
    }
    {   // relu + write intermediate transposed: sB[f][n], two STS.128
        float2 v0 = unpackf2(a01), v1 = unpackf2(a23);
        float2 v2 = unpackf2(a45), v3 = unpackf2(a67);
        float4 y0 = make_float4(fmaxf(v0.x, 0.0f), fmaxf(v0.y, 0.0f),
                                fmaxf(v1.x, 0.0f), fmaxf(v1.y, 0.0f));
        float4 y1 = make_float4(fmaxf(v2.x, 0.0f), fmaxf(v2.y, 0.0f),
                                fmaxf(v3.x, 0.0f), fmaxf(v3.y, 0.0f));
        *(float4*)&sB[f * 36 + g * 8]     = y0;
        *(float4*)&sB[f * 36 + g * 8 + 4] = y1;
    }
    __syncthreads();

    {
        float bb = b2[f];
        unsigned long long bp = packf2(bb, bb);
        a01 = bp; a23 = bp; a45 = bp; a67 = bp;
    }
#pragma unroll
    for (int k = 0; k < 64; k++) {
        float w = sW2[k * 64 + f];
        unsigned long long ww = packf2(w, w);
        ulonglong2 p0 = *(const ulonglong2*)&sB[k * 36 + g * 8];
        ulonglong2 p1 = *(const ulonglong2*)&sB[k * 36 + g * 8 + 4];
        a01 = fma2(p0.x, ww, a01); a23 = fma2(p0.y, ww, a23);
        a45 = fma2(p1.x, ww, a45); a67 = fma2(p1.y, ww, a67);
    }

    float out8[8];
    {
        float2 v0 = unpackf2(a01), v1 = unpackf2(a23);
        float2 v2 = unpackf2(a45), v3 = unpackf2(a67);
        out8[0] = v0.x; out8[1] = v0.y; out8[2] = v1.x; out8[3] = v1.y;
        out8[4] = v2.x; out8[5] = v2.y; out8[6] = v3.x; out8[7] = v3.y;
    }

    float s = 0.0f, qq = 0.0f;
    float* ga = (float*)g_a;
#pragma unroll
    for (int i = 0; i < 8; i++) {
        float v = fmaxf(out8[i], 0.0f);
        ga[(node0 + g * 8 + i) * 64 + f] = v;
        s += v;
        qq += v * v;
    }
    sred[f * 4 + g] = s;
    qred[f * 4 + g] = qq;
    __syncthreads();
    if (t < 64) {
        float ss = sred[t * 4] + sred[t * 4 + 1] + sred[t * 4 + 2] + sred[t * 4 + 3];
        float q2 = qred[t * 4] + qred[t * 4 + 1] + qred[t * 4 + 2] + qred[t * 4 + 3];
        atomicAdd(&g_stats[lidx * 128 + t], ss);
        atomicAdd(&g_stats[lidx * 128 + 64 + t], q2);
    }
}

// ---------------- final: BN(layer2) + relu + linear head --------------------
__global__ void k_final(const float* __restrict__ gamma, const float* __restrict__ beta,
                        const float* __restrict__ Wf, const float* __restrict__ bf,
                        float* __restrict__ out) {
    int t = threadIdx.x;
    int lane = t & 31;
    int node = blockIdx.x * 8 + (t >> 5);
    const float* ga = (const float*)g_a;
    float total = 0.0f;
#pragma unroll
    for (int half = 0; half < 2; half++) {
        int f = lane + 32 * half;
        float mu = g_stats[2 * 128 + f] * (1.0f / NN);
        float var = g_stats[2 * 128 + 64 + f] * (1.0f / NN) - mu * mu;
        float v = (ga[node * 64 + f] - mu) * rsqrtf(var + BN_EPS) * gamma[f] + beta[f];
        total += fmaxf(v, 0.0f) * Wf[f];
    }
#pragma unroll
    for (int off = 16; off > 0; off >>= 1)
        total += __shfl_down_sync(0xffffffffu, total, off);
    if (lane == 0) out[node] = total + bf[0];
}

// ---------------- launch ----------------------------------------------------
extern "C" void kernel_launch(void* const* d_in, const int* in_sizes, int n_in,
                              void* d_out, int out_size) {
    const float* x       = (const float*)d_in[0];
    const int*   lab     = (const int*)d_in[1];
    const int*   ei      = (const int*)d_in[2];
    const float* emb     = (const float*)d_in[3];
    const float* W1_0    = (const float*)d_in[4];
    const float* b1_0    = (const float*)d_in[5];
    const float* W2_0    = (const float*)d_in[6];
    const float* b2_0    = (const float*)d_in[7];
    const float* eps_0   = (const float*)d_in[8];
    const float* gamma_0 = (const float*)d_in[9];
    const float* beta_0  = (const float*)d_in[10];
    const float* W1_s    = (const float*)d_in[11];
    const float* b1_s    = (const float*)d_in[12];
    const float* W2_s    = (const float*)d_in[13];
    const float* b2_s    = (const float*)d_in[14];
    const float* eps_s   = (const float*)d_in[15];
    const float* gamma_s = (const float*)d_in[16];
    const float* beta_s  = (const float*)d_in[17];
    const float* Wf      = (const float*)d_in[18];
    const float* bf      = (const float*)d_in[19];
    float* out = (float*)d_out;

    const int*  srcp = ei;
    const int*  dstp = ei + NE;
    const int4* dst4 = (const int4*)(ei + NE);

    k_init_embed<<<(NN + 255) / 256, 256>>>(x, lab, emb);

    // CSR build (counting sort by dst); scanB folded into scanC
    k_hist<<<(NE / 4 + 255) / 256, 256>>>(dst4);
    k_scanA<<<NSCAN, 1024>>>();
    k_scanC<<<NSCAN, 1024>>>();
    k_scatter<<<(NE + 255) / 256, 256>>>(srcp, dstp);

    // layer 0
    k_agg0<<<(NN + 63) / 64, 256>>>(eps_0);
    k_mlp<10, 16><<<NN / 32, 256>>>(W1_0, b1_0, W2_0, b2_0, 0);

    // layer 1: BN(l0) -> fp16, fp16 gather aggregation (R5 shape)
    k_bnapply<<<(NN * 32 + 255) / 256, 256>>>(0, gamma_0, beta_0);
    k_aggh<<<NN / 32, 256>>>(eps_s + 0);
    k_mlp<64, 64><<<NN / 32, 256>>>(W1_s + 0 * 4096, b1_s + 0 * 64,
                                    W2_s + 0 * 4096, b2_s + 0 * 64, 1);

    // layer 2: BN(l1) -> fp16, fp16 gather aggregation (R5 shape)
    k_bnapply<<<(NN * 32 + 255) / 256, 256>>>(1, gamma_s + 0 * 64, beta_s + 0 * 64);
    k_aggh<<<NN / 32, 256>>>(eps_s + 1);
    k_mlp<64, 64><<<NN / 32, 256>>>(W1_s + 1 * 4096, b1_s + 1 * 64,
                                    W2_s + 1 * 4096, b2_s + 1 * 64, 2);

    // final head (BN of layer 2 fused)
    k_final<<<NN / 8, 256>>>(gamma_s + 1 * 64, beta_s + 1 * 64, Wf, bf, out);
}

// round 9
// speedup vs baseline: 1.1400x; 1.0676x over previous
#include <cuda_runtime.h>
#include <cuda_fp16.h>

#define NN 100000
#define NE 3200000
#define BN_EPS 1e-5f
#define NSCAN 98   // ceil((NN+1)/1024)

// ---------------- scratch (static device buffers) ---------------------------
__device__ float4 g_h0[NN * 4];     // padded input features [N,16] (10 used)
__device__ float4 g_b0[NN * 4];     // combined layer-0 MLP input [N,16]
__device__ float4 g_a[NN * 16];     // MLP output pre-BN (post relu2) [N,64] fp32
__device__ __half g_ah[NN * 64];    // post-BN+ReLU activations, fp16
__device__ int   g_deg[NN];
__device__ int   g_rowstart[NN + 1];
__device__ int   g_cursor[NN];
__device__ int   g_src_sorted[NE];
__device__ int   g_blocksums[NSCAN];
__device__ float g_stats[3 * 128];  // per layer: [0..63]=sum, [64..127]=sumsq

__device__ __forceinline__ float bnr(float v, float sc, float sh) {
    return fmaxf(fmaf(v, sc, sh), 0.0f);
}

// ---------------- packed f32x2 helpers (Blackwell FFMA2 path) ---------------
__device__ __forceinline__ unsigned long long packf2(float a, float b) {
    unsigned long long r;
    asm("mov.b64 %0, {%1, %2};" : "=l"(r) : "f"(a), "f"(b));
    return r;
}
__device__ __forceinline__ unsigned long long fma2(unsigned long long a,
                                                   unsigned long long b,
                                                   unsigned long long c) {
    unsigned long long d;
    asm("fma.rn.f32x2 %0, %1, %2, %3;" : "=l"(d) : "l"(a), "l"(b), "l"(c));
    return d;
}
__device__ __forceinline__ float2 unpackf2(unsigned long long v) {
    float2 r;
    asm("mov.b64 {%0, %1}, %2;" : "=f"(r.x), "=f"(r.y) : "l"(v));
    return r;
}

// ---------------- init + embed (fused) --------------------------------------
__global__ void k_init_embed(const float* __restrict__ x, const int* __restrict__ lab,
                             const float* __restrict__ emb) {
    int n = blockIdx.x * blockDim.x + threadIdx.x;
    if (n < 3 * 128) g_stats[n] = 0.0f;
    if (n >= NN) return;
    g_deg[n] = 0;
    const float* e = emb + lab[n] * 8;
    float x0 = x[2 * n], x1 = x[2 * n + 1];
    g_h0[n * 4 + 0] = make_float4(x0, x1, e[0], e[1]);
    g_h0[n * 4 + 1] = make_float4(e[2], e[3], e[4], e[5]);
    g_h0[n * 4 + 2] = make_float4(e[6], e[7], 0.0f, 0.0f);
    g_h0[n * 4 + 3] = make_float4(0.0f, 0.0f, 0.0f, 0.0f);
}

// ---------------- CSR build: histogram + scan + scatter ---------------------
__global__ void k_hist(const int4* __restrict__ dst4) {
    int e = blockIdx.x * blockDim.x + threadIdx.x;
    if (e >= NE / 4) return;
    int4 d = dst4[e];
    atomicAdd(&g_deg[d.x], 1);
    atomicAdd(&g_deg[d.y], 1);
    atomicAdd(&g_deg[d.z], 1);
    atomicAdd(&g_deg[d.w], 1);
}

__global__ void k_scanA() {
    __shared__ int sm[1024];
    int t = threadIdx.x;
    int i = blockIdx.x * 1024 + t;
    sm[t] = (i < NN) ? g_deg[i] : 0;
    __syncthreads();
    for (int off = 512; off > 0; off >>= 1) {
        if (t < off) sm[t] += sm[t + off];
        __syncthreads();
    }
    if (t == 0) g_blocksums[blockIdx.x] = sm[0];
}

// scanC: per-block offset computed inline from g_blocksums (no scanB kernel)
__global__ void k_scanC() {
    __shared__ int sm[1024];
    __shared__ int boff;
    int t = threadIdx.x;
    if (t == 0) boff = 0;
    __syncthreads();
    if (t < (int)blockIdx.x) atomicAdd(&boff, g_blocksums[t]);  // t < 98 implied
    int i = blockIdx.x * 1024 + t;
    int v = (i < NN) ? g_deg[i] : 0;
    sm[t] = v;
    __syncthreads();
    for (int off = 1; off < 1024; off <<= 1) {
        int add = (t >= off) ? sm[t - off] : 0;
        __syncthreads();
        sm[t] += add;
        __syncthreads();
    }
    int excl = boff + sm[t] - v;
    if (i <= NN) g_rowstart[i] = excl;
    if (i < NN)  g_cursor[i]   = excl;
}

__global__ void k_scatter(const int* __restrict__ src, const int* __restrict__ dst) {
    int e = blockIdx.x * blockDim.x + threadIdx.x;
    if (e >= NE) return;
    int p = atomicAdd(&g_cursor[dst[e]], 1);
    g_src_sorted[p] = src[e];
}

// ---------------- layer-0 aggregation (16-wide rows, fp32) ------------------
// 4 threads/node, float4 lanes, 64 nodes/block
__global__ void k_agg0(const float* __restrict__ eps_ptr) {
    int t = threadIdx.x;
    int node = blockIdx.x * 64 + (t >> 2);
    if (node >= NN) return;
    int q = t & 3;
    int s = g_rowstart[node], e = g_rowstart[node + 1];
    float4 a0 = {0, 0, 0, 0}, a1 = {0, 0, 0, 0}, a2 = {0, 0, 0, 0}, a3 = {0, 0, 0, 0};
    int j = s;
    for (; j + 3 < e; j += 4) {
        int s0 = g_src_sorted[j], s1 = g_src_sorted[j + 1];
        int s2 = g_src_sorted[j + 2], s3 = g_src_sorted[j + 3];
        float4 v0 = g_h0[s0 * 4 + q], v1 = g_h0[s1 * 4 + q];
        float4 v2 = g_h0[s2 * 4 + q], v3 = g_h0[s3 * 4 + q];
        a0.x += v0.x; a0.y += v0.y; a0.z += v0.z; a0.w += v0.w;
        a1.x += v1.x; a1.y += v1.y; a1.z += v1.z; a1.w += v1.w;
        a2.x += v2.x; a2.y += v2.y; a2.z += v2.z; a2.w += v2.w;
        a3.x += v3.x; a3.y += v3.y; a3.z += v3.z; a3.w += v3.w;
    }
    for (; j < e; j++) {
        float4 v = g_h0[g_src_sorted[j] * 4 + q];
        a0.x += v.x; a0.y += v.y; a0.z += v.z; a0.w += v.w;
    }
    float c = 1.0f + *eps_ptr;
    float4 w = g_h0[node * 4 + q];
    float4 o;
    o.x = c * w.x + a0.x + a1.x + a2.x + a3.x;
    o.y = c * w.y + a0.y + a1.y + a2.y + a3.y;
    o.z = c * w.z + a0.z + a1.z + a2.z + a3.z;
    o.w = c * w.w + a0.w + a1.w + a2.w + a3.w;
    g_b0[node * 4 + q] = o;
}

// ---------------- BN apply + ReLU -> fp16: g_a (fp32) -> g_ah (half) --------
__global__ void __launch_bounds__(256) k_bnapply(int lidx,
                                                 const float* __restrict__ gamma,
                                                 const float* __restrict__ beta) {
    __shared__ float ssc[64], ssh[64];
    int t = threadIdx.x;
    if (t < 64) {
        float mu = g_stats[lidx * 128 + t] * (1.0f / NN);
        float var = g_stats[lidx * 128 + 64 + t] * (1.0f / NN) - mu * mu;
        float r = rsqrtf(var + BN_EPS) * gamma[t];
        ssc[t] = r;
        ssh[t] = beta[t] - mu * r;
    }
    __syncthreads();
    int p = blockIdx.x * 256 + t;              // pair index, NN*32 total
    if (p >= NN * 32) return;
    int f2 = p & 31;                           // feature pair within row
    float2 v = ((const float2*)g_a)[p];
    float y0 = bnr(v.x, ssc[2 * f2], ssh[2 * f2]);
    float y1 = bnr(v.y, ssc[2 * f2 + 1], ssh[2 * f2 + 1]);
    ((__half2*)g_ah)[p] = __floats2half2_rn(y0, y1);
}

// ---------------- helpers for fp16 gather -----------------------------------
__device__ __forceinline__ void accum8(float* a, uint4 v) {
    const __half2* h = (const __half2*)&v;
#pragma unroll
    for (int i = 0; i < 4; i++) {
        float2 f = __half22float2(h[i]);
        a[2 * i]     += f.x;
        a[2 * i + 1] += f.y;
    }
}

// ---------------- FUSED layers 1,2: fp16 gather agg + 2-layer MLP -----------
// Block = 256 threads, 32 nodes.
// Phase A (agg, R5 shape): 8 thr/node, q = t&7 covers features 8q..8q+7.
//   Edge loop reads g_ah (LDG.128/edge-thread), fp32 accumulate, result goes
//   straight into the transposed smem tile sAB[k][n] (no gmem round-trip).
// Phase B (MLP): thread (f = t&63, g = t>>6) computes 8 nodes via FFMA2.
//   sAB is reused for the ReLU intermediate (extra barrier between phases).
__global__ void __launch_bounds__(256) k_aggmlp(const float* __restrict__ W1,
                                                const float* __restrict__ b1,
                                                const float* __restrict__ W2,
                                                const float* __restrict__ b2,
                                                const float* __restrict__ eps_ptr,
                                                int lidx) {
    __shared__ float sW1[64 * 64];
    __shared__ float sW2[64 * 64];
    __shared__ float sAB[64 * 36];    // [k][node], stride 36; overlaid A then B
    __shared__ float sred[256];
    __shared__ float qred[256];

    int t = threadIdx.x;
    int node0 = blockIdx.x * 32;

    // stage weights (overlaps with edge loop; no sync needed until phase B)
    for (int i = t; i < 64 * 16; i += 256)
        ((float4*)sW1)[i] = ((const float4*)W1)[i];
    for (int i = t; i < 64 * 16; i += 256)
        ((float4*)sW2)[i] = ((const float4*)W2)[i];

    // ---- Phase A: aggregation ----
    {
        int nloc = t >> 3;
        int q = t & 7;
        int node = node0 + nloc;
        const uint4* A = (const uint4*)g_ah;
        int s = g_rowstart[node], e = g_rowstart[node + 1];
        float a0[8] = {0, 0, 0, 0, 0, 0, 0, 0};
        float a1[8] = {0, 0, 0, 0, 0, 0, 0, 0};
        int j = s;
        for (; j + 3 < e; j += 4) {
            int s0 = g_src_sorted[j],     s1 = g_src_sorted[j + 1];
            int s2 = g_src_sorted[j + 2], s3 = g_src_sorted[j + 3];
            uint4 v0 = A[s0 * 8 + q], v1 = A[s1 * 8 + q];
            uint4 v2 = A[s2 * 8 + q], v3 = A[s3 * 8 + q];
            accum8(a0, v0); accum8(a1, v1); accum8(a0, v2); accum8(a1, v3);
        }
        for (; j < e; j++) accum8(a0, A[g_src_sorted[j] * 8 + q]);

        float c = 1.0f + *eps_ptr;
        uint4 w = A[node * 8 + q];
        const __half2* h = (const __half2*)&w;
#pragma unroll
        for (int i = 0; i < 4; i++) {
            float2 f = __half22float2(h[i]);
            float r0 = fmaf(c, f.x, a0[2 * i]     + a1[2 * i]);
            float r1 = fmaf(c, f.y, a0[2 * i + 1] + a1[2 * i + 1]);
            sAB[(q * 8 + 2 * i)     * 36 + nloc] = r0;
            sAB[(q * 8 + 2 * i + 1) * 36 + nloc] = r1;
        }
    }
    __syncthreads();

    // ---- Phase B: 2-layer MLP (FFMA2) ----
    int f = t & 63;
    int g = t >> 6;

    unsigned long long a01, a23, a45, a67;
    {
        float bb = b1[f];
        unsigned long long bp = packf2(bb, bb);
        a01 = bp; a23 = bp; a45 = bp; a67 = bp;
    }
#pragma unroll
    for (int k = 0; k < 64; k++) {
        float w = sW1[k * 64 + f];
        unsigned long long ww = packf2(w, w);
        ulonglong2 p0 = *(const ulonglong2*)&sAB[k * 36 + g * 8];
        ulonglong2 p1 = *(const ulonglong2*)&sAB[k * 36 + g * 8 + 4];
        a01 = fma2(p0.x, ww, a01); a23 = fma2(p0.y, ww, a23);
        a45 = fma2(p1.x, ww, a45); a67 = fma2(p1.y, ww, a67);
    }
    __syncthreads();   // all reads of sAB(A) done before overwrite
    {   // relu + write intermediate transposed: sAB[f][n], two STS.128
        float2 v0 = unpackf2(a01), v1 = unpackf2(a23);
        float2 v2 = unpackf2(a45), v3 = unpackf2(a67);
        float4 y0 = make_float4(fmaxf(v0.x, 0.0f), fmaxf(v0.y, 0.0f),
                                fmaxf(v1.x, 0.0f), fmaxf(v1.y, 0.0f));
        float4 y1 = make_float4(fmaxf(v2.x, 0.0f), fmaxf(v2.y, 0.0f),
                                fmaxf(v3.x, 0.0f), fmaxf(v3.y, 0.0f));
        *(float4*)&sAB[f * 36 + g * 8]     = y0;
        *(float4*)&sAB[f * 36 + g * 8 + 4] = y1;
    }
    __syncthreads();

    {
        float bb = b2[f];
        unsigned long long bp = packf2(bb, bb);
        a01 = bp; a23 = bp; a45 = bp; a67 = bp;
    }
#pragma unroll
    for (int k = 0; k < 64; k++) {
        float w = sW2[k * 64 + f];
        unsigned long long ww = packf2(w, w);
        ulonglong2 p0 = *(const ulonglong2*)&sAB[k * 36 + g * 8];
        ulonglong2 p1 = *(const ulonglong2*)&sAB[k * 36 + g * 8 + 4];
        a01 = fma2(p0.x, ww, a01); a23 = fma2(p0.y, ww, a23);
        a45 = fma2(p1.x, ww, a45); a67 = fma2(p1.y, ww, a67);
    }

    float out8[8];
    {
        float2 v0 = unpackf2(a01), v1 = unpackf2(a23);
        float2 v2 = unpackf2(a45), v3 = unpackf2(a67);
        out8[0] = v0.x; out8[1] = v0.y; out8[2] = v1.x; out8[3] = v1.y;
        out8[4] = v2.x; out8[5] = v2.y; out8[6] = v3.x; out8[7] = v3.y;
    }

    float s = 0.0f, qq = 0.0f;
    float* ga = (float*)g_a;
#pragma unroll
    for (int i = 0; i < 8; i++) {
        float v = fmaxf(out8[i], 0.0f);
        ga[(node0 + g * 8 + i) * 64 + f] = v;
        s += v;
        qq += v * v;
    }
    sred[f * 4 + g] = s;
    qred[f * 4 + g] = qq;
    __syncthreads();
    if (t < 64) {
        float ss = sred[t * 4] + sred[t * 4 + 1] + sred[t * 4 + 2] + sred[t * 4 + 3];
        float q2 = qred[t * 4] + qred[t * 4 + 1] + qred[t * 4 + 2] + qred[t * 4 + 3];
        atomicAdd(&g_stats[lidx * 128 + t], ss);
        atomicAdd(&g_stats[lidx * 128 + 64 + t], q2);
    }
}

// ---------------- layer-0 MLP (DIN=10, reads g_b0) --------------------------
__global__ void __launch_bounds__(256) k_mlp0(const float* __restrict__ W1,
                                              const float* __restrict__ b1,
                                              const float* __restrict__ W2,
                                              const float* __restrict__ b2) {
    __shared__ float sW1[10 * 64];
    __shared__ float sW2[64 * 64];
    __shared__ float sA[16 * 36];
    __shared__ float sB[64 * 36];
    __shared__ float sred[256];
    __shared__ float qred[256];

    int t = threadIdx.x;
    int f = t & 63;
    int g = t >> 6;
    int node0 = blockIdx.x * 32;

    for (int i = t; i < 10 * 16; i += 256)
        ((float4*)sW1)[i] = ((const float4*)W1)[i];
    for (int i = t; i < 64 * 16; i += 256)
        ((float4*)sW2)[i] = ((const float4*)W2)[i];
    for (int i = t; i < 32 * 4; i += 256) {
        int n = i / 4, kq = i % 4;
        float4 v = g_b0[(node0 + n) * 4 + kq];
        sA[(kq * 4 + 0) * 36 + n] = v.x;
        sA[(kq * 4 + 1) * 36 + n] = v.y;
        sA[(kq * 4 + 2) * 36 + n] = v.z;
        sA[(kq * 4 + 3) * 36 + n] = v.w;
    }
    __syncthreads();

    unsigned long long a01, a23, a45, a67;
    {
        float bb = b1[f];
        unsigned long long bp = packf2(bb, bb);
        a01 = bp; a23 = bp; a45 = bp; a67 = bp;
    }
#pragma unroll
    for (int k = 0; k < 10; k++) {
        float w = sW1[k * 64 + f];
        unsigned long long ww = packf2(w, w);
        ulonglong2 p0 = *(const ulonglong2*)&sA[k * 36 + g * 8];
        ulonglong2 p1 = *(const ulonglong2*)&sA[k * 36 + g * 8 + 4];
        a01 = fma2(p0.x, ww, a01); a23 = fma2(p0.y, ww, a23);
        a45 = fma2(p1.x, ww, a45); a67 = fma2(p1.y, ww, a67);
    }
    {
        float2 v0 = unpackf2(a01), v1 = unpackf2(a23);
        float2 v2 = unpackf2(a45), v3 = unpackf2(a67);
        float4 y0 = make_float4(fmaxf(v0.x, 0.0f), fmaxf(v0.y, 0.0f),
                                fmaxf(v1.x, 0.0f), fmaxf(v1.y, 0.0f));
        float4 y1 = make_float4(fmaxf(v2.x, 0.0f), fmaxf(v2.y, 0.0f),
                                fmaxf(v3.x, 0.0f), fmaxf(v3.y, 0.0f));
        *(float4*)&sB[f * 36 + g * 8]     = y0;
        *(float4*)&sB[f * 36 + g * 8 + 4] = y1;
    }
    __syncthreads();

    {
        float bb = b2[f];
        unsigned long long bp = packf2(bb, bb);
        a01 = bp; a23 = bp; a45 = bp; a67 = bp;
    }
#pragma unroll
    for (int k = 0; k < 64; k++) {
        float w = sW2[k * 64 + f];
        unsigned long long ww = packf2(w, w);
        ulonglong2 p0 = *(const ulonglong2*)&sB[k * 36 + g * 8];
        ulonglong2 p1 = *(const ulonglong2*)&sB[k * 36 + g * 8 + 4];
        a01 = fma2(p0.x, ww, a01); a23 = fma2(p0.y, ww, a23);
        a45 = fma2(p1.x, ww, a45); a67 = fma2(p1.y, ww, a67);
    }

    float out8[8];
    {
        float2 v0 = unpackf2(a01), v1 = unpackf2(a23);
        float2 v2 = unpackf2(a45), v3 = unpackf2(a67);
        out8[0] = v0.x; out8[1] = v0.y; out8[2] = v1.x; out8[3] = v1.y;
        out8[4] = v2.x; out8[5] = v2.y; out8[6] = v3.x; out8[7] = v3.y;
    }

    float s = 0.0f, qq = 0.0f;
    float* ga = (float*)g_a;
#pragma unroll
    for (int i = 0; i < 8; i++) {
        float v = fmaxf(out8[i], 0.0f);
        ga[(node0 + g * 8 + i) * 64 + f] = v;
        s += v;
        qq += v * v;
    }
    sred[f * 4 + g] = s;
    qred[f * 4 + g] = qq;
    __syncthreads();
    if (t < 64) {
        float ss = sred[t * 4] + sred[t * 4 + 1] + sred[t * 4 + 2] + sred[t * 4 + 3];
        float q2 = qred[t * 4] + qred[t * 4 + 1] + qred[t * 4 + 2] + qred[t * 4 + 3];
        atomicAdd(&g_stats[0 * 128 + t], ss);
        atomicAdd(&g_stats[0 * 128 + 64 + t], q2);
    }
}

// ---------------- final: BN(layer2) + relu + linear head --------------------
__global__ void k_final(const float* __restrict__ gamma, const float* __restrict__ beta,
                        const float* __restrict__ Wf, const float* __restrict__ bf,
                        float* __restrict__ out) {
    int t = threadIdx.x;
    int lane = t & 31;
    int node = blockIdx.x * 8 + (t >> 5);
    const float* ga = (const float*)g_a;
    float total = 0.0f;
#pragma unroll
    for (int half = 0; half < 2; half++) {
        int f = lane + 32 * half;
        float mu = g_stats[2 * 128 + f] * (1.0f / NN);
        float var = g_stats[2 * 128 + 64 + f] * (1.0f / NN) - mu * mu;
        float v = (ga[node * 64 + f] - mu) * rsqrtf(var + BN_EPS) * gamma[f] + beta[f];
        total += fmaxf(v, 0.0f) * Wf[f];
    }
#pragma unroll
    for (int off = 16; off > 0; off >>= 1)
        total += __shfl_down_sync(0xffffffffu, total, off);
    if (lane == 0) out[node] = total + bf[0];
}

// ---------------- launch ----------------------------------------------------
extern "C" void kernel_launch(void* const* d_in, const int* in_sizes, int n_in,
                              void* d_out, int out_size) {
    const float* x       = (const float*)d_in[0];
    const int*   lab     = (const int*)d_in[1];
    const int*   ei      = (const int*)d_in[2];
    const float* emb     = (const float*)d_in[3];
    const float* W1_0    = (const float*)d_in[4];
    const float* b1_0    = (const float*)d_in[5];
    const float* W2_0    = (const float*)d_in[6];
    const float* b2_0    = (const float*)d_in[7];
    const float* eps_0   = (const float*)d_in[8];
    const float* gamma_0 = (const float*)d_in[9];
    const float* beta_0  = (const float*)d_in[10];
    const float* W1_s    = (const float*)d_in[11];
    const float* b1_s    = (const float*)d_in[12];
    const float* W2_s    = (const float*)d_in[13];
    const float* b2_s    = (const float*)d_in[14];
    const float* eps_s   = (const float*)d_in[15];
    const float* gamma_s = (const float*)d_in[16];
    const float* beta_s  = (const float*)d_in[17];
    const float* Wf      = (const float*)d_in[18];
    const float* bf      = (const float*)d_in[19];
    float* out = (float*)d_out;

    const int*  srcp = ei;
    const int*  dstp = ei + NE;
    const int4* dst4 = (const int4*)(ei + NE);

    k_init_embed<<<(NN + 255) / 256, 256>>>(x, lab, emb);

    // CSR build (counting sort by dst); scanB folded into scanC
    k_hist<<<(NE / 4 + 255) / 256, 256>>>(dst4);
    k_scanA<<<NSCAN, 1024>>>();
    k_scanC<<<NSCAN, 1024>>>();
    k_scatter<<<(NE + 255) / 256, 256>>>(srcp, dstp);

    // layer 0
    k_agg0<<<(NN + 63) / 64, 256>>>(eps_0);
    k_mlp0<<<NN / 32, 256>>>(W1_0, b1_0, W2_0, b2_0);

    // layer 1: BN(l0) -> fp16, fused agg+MLP
    k_bnapply<<<(NN * 32 + 255) / 256, 256>>>(0, gamma_0, beta_0);
    k_aggmlp<<<NN / 32, 256>>>(W1_s + 0 * 4096, b1_s + 0 * 64,
                               W2_s + 0 * 4096, b2_s + 0 * 64, eps_s + 0, 1);

    // layer 2: BN(l1) -> fp16, fused agg+MLP
    k_bnapply<<<(NN * 32 + 255) / 256, 256>>>(1, gamma_s + 0 * 64, beta_s + 0 * 64);
    k_aggmlp<<<NN / 32, 256>>>(W1_s + 1 * 4096, b1_s + 1 * 64,
                               W2_s + 1 * 4096, b2_s + 1 * 64, eps_s + 1, 2);

    // final head (BN of layer 2 fused)
    k_final<<<NN / 8, 256>>>(gamma_s + 1 * 64, beta_s + 1 * 64, Wf, bf, out);
}